// round 7
// baseline (speedup 1.0000x reference)
#include <cuda_runtime.h>

#define BZ   32
#define CAP  134
#define SEQ  144
#define INV  16
#define E_SP 1072
#define E_FT 64
#define NTHR 160
#define XSTR 160
#define YSTR 20      // padded row stride for sYA/sYF
#define TCH  8       // t-rows of W staged per chunk (SEQ % TCH == 0)

// ---------------- device-global precomputed state (no cudaMalloc allowed) ----
__device__ int    g_rowptr[CAP + 1];
__device__ int    g_col[E_SP];
__device__ float  g_invdeg[CAP];
__device__ float  g_G1[INV][INV];   // Wl @ F1
__device__ float  g_G2[INV][INV];   // Wr @ F1
__device__ float  g_B1[INV][INV];   // A^T @ F2
__device__ float  g_F2[INV][INV];   // F2
__device__ float  g_V[5][INV][INV]; // combined conv taps folded with F3
__device__ float  g_csF2[INV];      // column sums of F2 (for fgcn_bl term)
__device__ float  g_const[INV];     // bl@F1 + fc_b
__device__ float2 g_W2[SEQ * SEQ];  // packed (fWl[t][s], fWr[t][s]), row t contiguous in s

// ---------------- prep kernel: edge-parallel deterministic CSR --------------
__global__ void prep_kernel(const int* __restrict__ gei, const int* __restrict__ fei,
                            const float* __restrict__ Wl, const float* __restrict__ bl,
                            const float* __restrict__ Wr,
                            const float* __restrict__ c1w, const float* __restrict__ c2w,
                            const float* __restrict__ fcw, const float* __restrict__ fcb) {
    const int tid = threadIdx.x; // 1024 threads
    __shared__ int   s_src[E_SP];
    __shared__ int   s_dst[E_SP];
    __shared__ int   s_deg[CAP];
    __shared__ int   s_row[CAP + 1];
    __shared__ int   s_cnt[INV][INV];
    __shared__ float s_A[INV][INV];

    for (int e = tid; e < E_SP; e += 1024) {
        s_src[e] = gei[e];
        s_dst[e] = gei[E_SP + e];
    }
    if (tid < CAP) s_deg[tid] = 0;
    __syncthreads();

    // degree via smem atomics (counts are deterministic)
    for (int e = tid; e < E_SP; e += 1024)
        atomicAdd(&s_deg[s_dst[e]], 1);
    __syncthreads();

    if (tid == 0) {
        int acc = 0;
        for (int c = 0; c < CAP; c++) { s_row[c] = acc; acc += s_deg[c]; }
        s_row[CAP] = acc;
    }
    __syncthreads();

    if (tid < CAP) {
        g_rowptr[tid] = s_row[tid];
        g_invdeg[tid] = 1.0f / fmaxf((float)s_deg[tid], 1.0f);
        if (tid == 0) g_rowptr[CAP] = s_row[CAP];
    }

    // edge-parallel CSR fill: position = rowptr[dst] + #{e' < e : dst[e']==dst[e]}
    for (int e = tid; e < E_SP; e += 1024) {
        int d = s_dst[e];
        int cnt = 0;
        for (int e2 = 0; e2 < e; e2++) cnt += (s_dst[e2] == d);
        g_col[s_row[d] + cnt] = s_src[e];
    }

    // feature adjacency (16x16 dense) from E_FT=64 edges
    if (tid < 256) {
        int i = tid >> 4, j = tid & 15;
        int cnt = 0;
        for (int e = 0; e < E_FT; e++)
            if (fei[E_FT + e] == i && fei[e] == j) cnt++;
        s_cnt[i][j] = cnt;
    }
    __syncthreads();
    if (tid < 256) {
        int i = tid >> 4, j = tid & 15;
        int dsum = 0;
        for (int jj = 0; jj < INV; jj++) dsum += s_cnt[i][jj];
        s_A[i][j] = (float)s_cnt[i][j] / fmaxf((float)dsum, 1.0f);
    }
    __syncthreads();
    if (tid < 256) {
        int r = tid >> 4, o = tid & 15;
        float g1 = 0.f, g2 = 0.f, b1 = 0.f;
        for (int i = 0; i < INV; i++) {
            float f1 = fcw[i * INV + o];
            float f2 = fcw[(INV + i) * INV + o];
            g1 += Wl[r * INV + i] * f1;
            g2 += Wr[r * INV + i] * f1;
            b1 += s_A[i][r] * f2;
        }
        g_G1[r][o] = g1; g_G2[r][o] = g2; g_B1[r][o] = b1;
        g_F2[r][o] = fcw[(INV + r) * INV + o];
        for (int k = 0; k < 5; k++) {
            float v = 0.f;
            for (int o2 = 0; o2 < INV; o2++) {
                float w5 = c2w[(o2 * INV + r) * 5 + k];
                if (k >= 1 && k <= 3) w5 += c1w[(o2 * INV + r) * 3 + (k - 1)];
                v += w5 * fcw[(32 + o2) * INV + o];
            }
            g_V[k][r][o] = v;
        }
        if (r == 0) {
            float cs = 0.f, cv = 0.f;
            for (int i = 0; i < INV; i++) {
                cs += fcw[(INV + i) * INV + o];
                cv += bl[i] * fcw[i * INV + o];
            }
            g_csF2[o] = cs;
            g_const[o] = cv + fcb[o];
        }
    }
}

// pack (fWl, fWr) interleaved: g_W2[t*SEQ+s] = (fWl[t][s], fWr[t][s])
__global__ void w2_kernel(const float* __restrict__ fWl, const float* __restrict__ fWr) {
    int i = blockIdx.x * blockDim.x + threadIdx.x;
    if (i < SEQ * SEQ) g_W2[i] = make_float2(fWl[i], fWr[i]);
}

// ---------------- main fused kernel: one (b,c) slice per block --------------
__global__ __launch_bounds__(NTHR, 4)
void stconv_kernel(const float* __restrict__ src,
                   const float* __restrict__ fbl,
                   float* __restrict__ out) {
    __shared__ __align__(16) float  sX[INV][XSTR];     // transposed X: sX[i][s]
    __shared__ __align__(16) float  sYA[SEQ][YSTR];    // X @ (A^T F2)
    __shared__ __align__(16) float  sYF[SEQ][YSTR];    // X @ F2
    __shared__ __align__(16) float  sG1[INV][INV], sG2[INV][INV], sB1[INV][INV], sF2[INV][INV];
    __shared__ __align__(16) float  sV[5][INV][INV];
    __shared__ __align__(16) float2 sW[TCH * SEQ];     // staged W rows (t-chunk)
    __shared__ float sCs[INV], sC0[INV];

    const int c = blockIdx.x, b = blockIdx.y;
    const int tid = threadIdx.x;
    const int s = tid;
    const int base = ((b * CAP + c) * SEQ) * INV;

    for (int idx = tid; idx < INV * INV; idx += NTHR) {
        int r = idx >> 4, o = idx & 15;
        sG1[r][o] = g_G1[r][o]; sG2[r][o] = g_G2[r][o];
        sB1[r][o] = g_B1[r][o]; sF2[r][o] = g_F2[r][o];
        #pragma unroll
        for (int k = 0; k < 5; k++) sV[k][r][o] = g_V[k][r][o];
        if (r == 0) { sCs[o] = g_csF2[o]; sC0[o] = g_const[o]; }
    }

    if (s < SEQ) {
        const float4* p = (const float4*)(src + base + s * INV);
        float4 a0 = p[0], a1 = p[1], a2 = p[2], a3 = p[3];
        sX[0][s]=a0.x;  sX[1][s]=a0.y;  sX[2][s]=a0.z;  sX[3][s]=a0.w;
        sX[4][s]=a1.x;  sX[5][s]=a1.y;  sX[6][s]=a1.z;  sX[7][s]=a1.w;
        sX[8][s]=a2.x;  sX[9][s]=a2.y;  sX[10][s]=a2.z; sX[11][s]=a2.w;
        sX[12][s]=a3.x; sX[13][s]=a3.y; sX[14][s]=a3.z; sX[15][s]=a3.w;
    }
    __syncthreads();

    float acc[16];
    if (s < SEQ) {
        // YA = X @ B1, YF = X @ F2 (row s) -> smem for the big-GEMM phase
        {
            float ya[16], yf[16];
            #pragma unroll
            for (int o = 0; o < 16; o++) { ya[o] = 0.f; yf[o] = 0.f; }
            #pragma unroll
            for (int j = 0; j < 16; j++) {
                float xv = sX[j][s];
                #pragma unroll
                for (int o = 0; o < 16; o++) {
                    ya[o] += xv * sB1[j][o];
                    yf[o] += xv * sF2[j][o];
                }
            }
            #pragma unroll
            for (int o = 0; o < 16; o++) { sYA[s][o] = ya[o]; sYF[s][o] = yf[o]; }
        }

        // constant + fgcn_bl term
        float fblv = __ldg(fbl + s);
        #pragma unroll
        for (int o = 0; o < 16; o++) acc[o] = sC0[o] + fblv * sCs[o];

        // spatial: gather mean over graph neighbors of c
        {
            int r0 = g_rowptr[c], r1 = g_rowptr[c + 1];
            float mg[16];
            #pragma unroll
            for (int o = 0; o < 16; o++) mg[o] = 0.f;
            for (int e = r0; e < r1; e++) {
                int nb = g_col[e];
                const float4* p = (const float4*)(src + ((b * CAP + nb) * SEQ + s) * INV);
                float4 a0 = __ldg(p), a1 = __ldg(p + 1), a2 = __ldg(p + 2), a3 = __ldg(p + 3);
                mg[0]+=a0.x; mg[1]+=a0.y; mg[2]+=a0.z; mg[3]+=a0.w;
                mg[4]+=a1.x; mg[5]+=a1.y; mg[6]+=a1.z; mg[7]+=a1.w;
                mg[8]+=a2.x; mg[9]+=a2.y; mg[10]+=a2.z; mg[11]+=a2.w;
                mg[12]+=a3.x; mg[13]+=a3.y; mg[14]+=a3.z; mg[15]+=a3.w;
            }
            float sc = g_invdeg[c];
            #pragma unroll
            for (int j = 0; j < 16; j++) {
                float m = mg[j] * sc;
                float xv = sX[j][s];
                #pragma unroll
                for (int o = 0; o < 16; o++) acc[o] += m * sG1[j][o] + xv * sG2[j][o];
            }
        }

        // temporal: combined 5-tap conv with F3 folded in
        #pragma unroll
        for (int k = 0; k < 5; k++) {
            int sp = s + k - 2;
            if (sp >= 0 && sp < SEQ) {
                #pragma unroll
                for (int j = 0; j < 16; j++) {
                    float xv = sX[j][sp];
                    #pragma unroll
                    for (int o = 0; o < 16; o++) acc[o] += xv * sV[k][j][o];
                }
            }
        }
    }
    __syncthreads();

    // big GEMM with W staged through smem in chunks of TCH rows.
    // g_W2 rows are contiguous: chunk copy is one coalesced linear memcpy.
    for (int t0 = 0; t0 < SEQ; t0 += TCH) {
        const float2* wsrc = g_W2 + t0 * SEQ;
        for (int i = tid; i < TCH * SEQ; i += NTHR) sW[i] = wsrc[i];
        __syncthreads();
        if (s < SEQ) {
            #pragma unroll
            for (int tt = 0; tt < TCH; tt++) {
                float2 w = sW[tt * SEQ + s];
                float a = w.x, bb = w.y;
                const int t = t0 + tt;
                const float4* yap = (const float4*)sYA[t];
                const float4* yfp = (const float4*)sYF[t];
                float4 u0 = yap[0], u1 = yap[1], u2 = yap[2], u3 = yap[3];
                float4 v0 = yfp[0], v1 = yfp[1], v2 = yfp[2], v3 = yfp[3];
                acc[0]  += a*u0.x + bb*v0.x;  acc[1]  += a*u0.y + bb*v0.y;
                acc[2]  += a*u0.z + bb*v0.z;  acc[3]  += a*u0.w + bb*v0.w;
                acc[4]  += a*u1.x + bb*v1.x;  acc[5]  += a*u1.y + bb*v1.y;
                acc[6]  += a*u1.z + bb*v1.z;  acc[7]  += a*u1.w + bb*v1.w;
                acc[8]  += a*u2.x + bb*v2.x;  acc[9]  += a*u2.y + bb*v2.y;
                acc[10] += a*u2.z + bb*v2.z;  acc[11] += a*u2.w + bb*v2.w;
                acc[12] += a*u3.x + bb*v3.x;  acc[13] += a*u3.y + bb*v3.y;
                acc[14] += a*u3.z + bb*v3.z;  acc[15] += a*u3.w + bb*v3.w;
            }
        }
        __syncthreads();
    }

    if (s < SEQ) {
        // out = src + contributions (x re-read from smem)
        float4* po = (float4*)(out + base + s * INV);
        po[0] = make_float4(sX[0][s]+acc[0],   sX[1][s]+acc[1],   sX[2][s]+acc[2],   sX[3][s]+acc[3]);
        po[1] = make_float4(sX[4][s]+acc[4],   sX[5][s]+acc[5],   sX[6][s]+acc[6],   sX[7][s]+acc[7]);
        po[2] = make_float4(sX[8][s]+acc[8],   sX[9][s]+acc[9],   sX[10][s]+acc[10], sX[11][s]+acc[11]);
        po[3] = make_float4(sX[12][s]+acc[12], sX[13][s]+acc[13], sX[14][s]+acc[14], sX[15][s]+acc[15]);
    }
}

// ---------------- launch ----------------------------------------------------
extern "C" void kernel_launch(void* const* d_in, const int* in_sizes, int n_in,
                              void* d_out, int out_size) {
    const float* src = (const float*)d_in[0];
    const int*   gei = (const int*)d_in[1];
    const int*   fei = (const int*)d_in[2];
    const float* Wl  = (const float*)d_in[3];
    const float* bl  = (const float*)d_in[4];
    const float* Wr  = (const float*)d_in[5];
    const float* fWl = (const float*)d_in[6];
    const float* fbl = (const float*)d_in[7];
    const float* fWr = (const float*)d_in[8];
    const float* c1w = (const float*)d_in[9];
    const float* c2w = (const float*)d_in[10];
    const float* fcw = (const float*)d_in[11];
    const float* fcb = (const float*)d_in[12];

    prep_kernel<<<1, 1024>>>(gei, fei, Wl, bl, Wr, c1w, c2w, fcw, fcb);
    w2_kernel<<<(SEQ * SEQ + 255) / 256, 256>>>(fWl, fWr);
    dim3 grid(CAP, BZ);
    stconv_kernel<<<grid, NTHR>>>(src, fbl, (float*)d_out);
}

// round 8
// speedup vs baseline: 1.1519x; 1.1519x over previous
#include <cuda_runtime.h>

#define BZ   32
#define CAP  134
#define SEQ  144
#define INV  16
#define E_SP 1072
#define E_FT 64
#define NTHR 160
#define XSTR 160
#define YSTR 20   // padded row stride for sYA/sYF

// ---------------- device-global precomputed state (no cudaMalloc allowed) ----
__device__ int    g_rowptr[CAP + 1];
__device__ int    g_col[E_SP];
__device__ float  g_invdeg[CAP];
__device__ float  g_G1[INV][INV];   // Wl @ F1
__device__ float  g_G2[INV][INV];   // Wr @ F1
__device__ float  g_B1[INV][INV];   // A^T @ F2
__device__ float  g_F2[INV][INV];   // F2
__device__ float  g_V[5][INV][INV]; // combined conv taps folded with F3
__device__ float  g_csF2[INV];      // column sums of F2 (for fgcn_bl term)
__device__ float  g_const[INV];     // bl@F1 + fc_b
__device__ float2 g_W2[SEQ * SEQ];  // packed (fWl[t][s], fWr[t][s])

// ---------------- fused prep: block 0 = CSR + folded matrices (all smem),
// ---------------- blocks 1..81 = W2 packing (81*256 == SEQ*SEQ) -------------
__global__ void prep_all(const int* __restrict__ gei, const int* __restrict__ fei,
                         const float* __restrict__ Wl, const float* __restrict__ bl,
                         const float* __restrict__ Wr,
                         const float* __restrict__ c1w, const float* __restrict__ c2w,
                         const float* __restrict__ fcw, const float* __restrict__ fcb,
                         const float* __restrict__ fWl, const float* __restrict__ fWr) {
    const int tid = threadIdx.x;   // 256 threads
    const int bx  = blockIdx.x;

    if (bx > 0) {
        int i = (bx - 1) * 256 + tid;   // exactly covers SEQ*SEQ = 20736
        g_W2[i] = make_float2(fWl[i], fWr[i]);
        return;
    }

    // ---- block 0: everything staged to smem first ----
    __shared__ int   s_src[E_SP];
    __shared__ int   s_dst[E_SP];
    __shared__ int   s_deg[CAP];
    __shared__ int   sc_a[256], sc_b[256];
    __shared__ int   s_fe[2 * E_FT];
    __shared__ int   s_cnt[INV][INV];
    __shared__ float s_A[INV][INV];
    __shared__ float s_fcw[48 * INV];
    __shared__ float s_Wl[INV * INV], s_Wr[INV * INV], s_bl[INV], s_fcb[INV];
    __shared__ float s_c1[INV * INV * 3], s_c2[INV * INV * 5];

    for (int e = tid; e < E_SP; e += 256) { s_src[e] = gei[e]; s_dst[e] = gei[E_SP + e]; }
    for (int i = tid; i < 2 * E_FT; i += 256) s_fe[i] = fei[i];
    for (int i = tid; i < 48 * INV; i += 256) s_fcw[i] = fcw[i];
    for (int i = tid; i < INV * INV; i += 256) { s_Wl[i] = Wl[i]; s_Wr[i] = Wr[i]; }
    for (int i = tid; i < INV * INV * 3; i += 256) s_c1[i] = c1w[i];
    for (int i = tid; i < INV * INV * 5; i += 256) s_c2[i] = c2w[i];
    if (tid < INV) { s_bl[tid] = bl[tid]; s_fcb[tid] = fcb[tid]; }
    if (tid < CAP) s_deg[tid] = 0;
    __syncthreads();

    // degree via smem atomics (deterministic counts)
    for (int e = tid; e < E_SP; e += 256) atomicAdd(&s_deg[s_dst[e]], 1);
    __syncthreads();

    // parallel inclusive scan over 256 padded entries (Hillis-Steele, ping-pong)
    int v = (tid < CAP) ? s_deg[tid] : 0;
    sc_a[tid] = v;
    __syncthreads();
    int* cur = sc_a; int* nxt = sc_b;
    #pragma unroll
    for (int off = 1; off < 256; off <<= 1) {
        int x = cur[tid];
        if (tid >= off) x += cur[tid - off];
        nxt[tid] = x;
        __syncthreads();
        int* t = cur; cur = nxt; nxt = t;
    }
    int incl = cur[tid];
    int excl = incl - v;
    if (tid < CAP) {
        g_rowptr[tid] = excl;
        g_invdeg[tid] = 1.0f / fmaxf((float)v, 1.0f);
        if (tid == CAP - 1) g_rowptr[CAP] = incl;
    }

    // per-node CSR fill (edge order preserved -> deterministic)
    if (tid < CAP) {
        int k = excl;
        #pragma unroll 8
        for (int e = 0; e < E_SP; e++)
            if (s_dst[e] == tid) g_col[k++] = s_src[e];
    }

    // feature adjacency (16x16 dense) from smem edge list
    {
        int i = tid >> 4, j = tid & 15;
        int cnt = 0;
        #pragma unroll
        for (int e = 0; e < E_FT; e++)
            if (s_fe[E_FT + e] == i && s_fe[e] == j) cnt++;
        s_cnt[i][j] = cnt;
    }
    __syncthreads();
    {
        int i = tid >> 4, j = tid & 15;
        int dsum = 0;
        #pragma unroll
        for (int jj = 0; jj < INV; jj++) dsum += s_cnt[i][jj];
        s_A[i][j] = (float)s_cnt[i][j] / fmaxf((float)dsum, 1.0f);
    }
    __syncthreads();

    // folded matrices (all operands in smem)
    {
        int r = tid >> 4, o = tid & 15;
        float g1 = 0.f, g2 = 0.f, b1 = 0.f;
        #pragma unroll
        for (int i = 0; i < INV; i++) {
            float f1 = s_fcw[i * INV + o];
            float f2 = s_fcw[(INV + i) * INV + o];
            g1 += s_Wl[r * INV + i] * f1;
            g2 += s_Wr[r * INV + i] * f1;
            b1 += s_A[i][r] * f2;
        }
        g_G1[r][o] = g1; g_G2[r][o] = g2; g_B1[r][o] = b1;
        g_F2[r][o] = s_fcw[(INV + r) * INV + o];
        #pragma unroll
        for (int k = 0; k < 5; k++) {
            float vv = 0.f;
            #pragma unroll
            for (int o2 = 0; o2 < INV; o2++) {
                float w5 = s_c2[(o2 * INV + r) * 5 + k];
                if (k >= 1 && k <= 3) w5 += s_c1[(o2 * INV + r) * 3 + (k - 1)];
                vv += w5 * s_fcw[(32 + o2) * INV + o];
            }
            g_V[k][r][o] = vv;
        }
        if (r == 0) {
            float cs = 0.f, cv = 0.f;
            #pragma unroll
            for (int i = 0; i < INV; i++) {
                cs += s_fcw[(INV + i) * INV + o];
                cv += s_bl[i] * s_fcw[i * INV + o];
            }
            g_csF2[o] = cs;
            g_const[o] = cv + s_fcb[o];
        }
    }
}

// ---------------- main fused kernel: one (b,c) slice per block --------------
// R4 structure (best measured); occupancy raised to 5 blocks/SM.
__global__ __launch_bounds__(NTHR, 5)
void stconv_kernel(const float* __restrict__ src,
                   const float* __restrict__ fbl,
                   float* __restrict__ out) {
    __shared__ __align__(16) float sX[INV][XSTR];      // transposed X: sX[i][s]
    __shared__ __align__(16) float sYA[SEQ][YSTR];     // X @ (A^T F2)
    __shared__ __align__(16) float sYF[SEQ][YSTR];     // X @ F2
    __shared__ __align__(16) float sG1[INV][INV], sG2[INV][INV], sB1[INV][INV], sF2[INV][INV];
    __shared__ __align__(16) float sV[5][INV][INV];
    __shared__ float sCs[INV], sC0[INV];

    const int c = blockIdx.x, b = blockIdx.y;
    const int tid = threadIdx.x;
    const int s = tid;
    const int base = ((b * CAP + c) * SEQ) * INV;

    for (int idx = tid; idx < INV * INV; idx += NTHR) {
        int r = idx >> 4, o = idx & 15;
        sG1[r][o] = g_G1[r][o]; sG2[r][o] = g_G2[r][o];
        sB1[r][o] = g_B1[r][o]; sF2[r][o] = g_F2[r][o];
        #pragma unroll
        for (int k = 0; k < 5; k++) sV[k][r][o] = g_V[k][r][o];
        if (r == 0) { sCs[o] = g_csF2[o]; sC0[o] = g_const[o]; }
    }

    if (s < SEQ) {
        const float4* p = (const float4*)(src + base + s * INV);
        float4 a0 = p[0], a1 = p[1], a2 = p[2], a3 = p[3];
        sX[0][s]=a0.x;  sX[1][s]=a0.y;  sX[2][s]=a0.z;  sX[3][s]=a0.w;
        sX[4][s]=a1.x;  sX[5][s]=a1.y;  sX[6][s]=a1.z;  sX[7][s]=a1.w;
        sX[8][s]=a2.x;  sX[9][s]=a2.y;  sX[10][s]=a2.z; sX[11][s]=a2.w;
        sX[12][s]=a3.x; sX[13][s]=a3.y; sX[14][s]=a3.z; sX[15][s]=a3.w;
    }
    __syncthreads();

    float acc[16];
    if (s < SEQ) {
        // YA = X @ B1, YF = X @ F2 (row s) -> smem for the big-GEMM phase
        {
            float ya[16], yf[16];
            #pragma unroll
            for (int o = 0; o < 16; o++) { ya[o] = 0.f; yf[o] = 0.f; }
            #pragma unroll
            for (int j = 0; j < 16; j++) {
                float xv = sX[j][s];
                #pragma unroll
                for (int o = 0; o < 16; o++) {
                    ya[o] += xv * sB1[j][o];
                    yf[o] += xv * sF2[j][o];
                }
            }
            #pragma unroll
            for (int o = 0; o < 16; o++) { sYA[s][o] = ya[o]; sYF[s][o] = yf[o]; }
        }

        // constant + fgcn_bl term
        float fblv = __ldg(fbl + s);
        #pragma unroll
        for (int o = 0; o < 16; o++) acc[o] = sC0[o] + fblv * sCs[o];

        // spatial: gather mean over graph neighbors of c
        {
            int r0 = g_rowptr[c], r1 = g_rowptr[c + 1];
            float mg[16];
            #pragma unroll
            for (int o = 0; o < 16; o++) mg[o] = 0.f;
            for (int e = r0; e < r1; e++) {
                int nb = g_col[e];
                const float4* p = (const float4*)(src + ((b * CAP + nb) * SEQ + s) * INV);
                float4 a0 = __ldg(p), a1 = __ldg(p + 1), a2 = __ldg(p + 2), a3 = __ldg(p + 3);
                mg[0]+=a0.x; mg[1]+=a0.y; mg[2]+=a0.z; mg[3]+=a0.w;
                mg[4]+=a1.x; mg[5]+=a1.y; mg[6]+=a1.z; mg[7]+=a1.w;
                mg[8]+=a2.x; mg[9]+=a2.y; mg[10]+=a2.z; mg[11]+=a2.w;
                mg[12]+=a3.x; mg[13]+=a3.y; mg[14]+=a3.z; mg[15]+=a3.w;
            }
            float sc = g_invdeg[c];
            #pragma unroll
            for (int j = 0; j < 16; j++) {
                float m = mg[j] * sc;
                float xv = sX[j][s];
                #pragma unroll
                for (int o = 0; o < 16; o++) acc[o] += m * sG1[j][o] + xv * sG2[j][o];
            }
        }

        // temporal: combined 5-tap conv with F3 folded in
        #pragma unroll
        for (int k = 0; k < 5; k++) {
            int sp = s + k - 2;
            if (sp >= 0 && sp < SEQ) {
                #pragma unroll
                for (int j = 0; j < 16; j++) {
                    float xv = sX[j][sp];
                    #pragma unroll
                    for (int o = 0; o < 16; o++) acc[o] += xv * sV[k][j][o];
                }
            }
        }
    }
    __syncthreads();

    if (s < SEQ) {
        // big GEMM: acc += sum_t fWl[t][s]*YA[t][:] + fWr[t][s]*YF[t][:]
        const float2* wp = g_W2 + s;
        #pragma unroll 4
        for (int t = 0; t < SEQ; t++) {
            float2 w = __ldg(wp + t * SEQ);
            float a = w.x, bb = w.y;
            const float4* yap = (const float4*)sYA[t];
            const float4* yfp = (const float4*)sYF[t];
            float4 u0 = yap[0], u1 = yap[1], u2 = yap[2], u3 = yap[3];
            float4 v0 = yfp[0], v1 = yfp[1], v2 = yfp[2], v3 = yfp[3];
            acc[0]  += a*u0.x + bb*v0.x;  acc[1]  += a*u0.y + bb*v0.y;
            acc[2]  += a*u0.z + bb*v0.z;  acc[3]  += a*u0.w + bb*v0.w;
            acc[4]  += a*u1.x + bb*v1.x;  acc[5]  += a*u1.y + bb*v1.y;
            acc[6]  += a*u1.z + bb*v1.z;  acc[7]  += a*u1.w + bb*v1.w;
            acc[8]  += a*u2.x + bb*v2.x;  acc[9]  += a*u2.y + bb*v2.y;
            acc[10] += a*u2.z + bb*v2.z;  acc[11] += a*u2.w + bb*v2.w;
            acc[12] += a*u3.x + bb*v3.x;  acc[13] += a*u3.y + bb*v3.y;
            acc[14] += a*u3.z + bb*v3.z;  acc[15] += a*u3.w + bb*v3.w;
        }

        // out = src + contributions (x re-read from smem)
        float4* po = (float4*)(out + base + s * INV);
        po[0] = make_float4(sX[0][s]+acc[0],   sX[1][s]+acc[1],   sX[2][s]+acc[2],   sX[3][s]+acc[3]);
        po[1] = make_float4(sX[4][s]+acc[4],   sX[5][s]+acc[5],   sX[6][s]+acc[6],   sX[7][s]+acc[7]);
        po[2] = make_float4(sX[8][s]+acc[8],   sX[9][s]+acc[9],   sX[10][s]+acc[10], sX[11][s]+acc[11]);
        po[3] = make_float4(sX[12][s]+acc[12], sX[13][s]+acc[13], sX[14][s]+acc[14], sX[15][s]+acc[15]);
    }
}

// ---------------- launch ----------------------------------------------------
extern "C" void kernel_launch(void* const* d_in, const int* in_sizes, int n_in,
                              void* d_out, int out_size) {
    const float* src = (const float*)d_in[0];
    const int*   gei = (const int*)d_in[1];
    const int*   fei = (const int*)d_in[2];
    const float* Wl  = (const float*)d_in[3];
    const float* bl  = (const float*)d_in[4];
    const float* Wr  = (const float*)d_in[5];
    const float* fWl = (const float*)d_in[6];
    const float* fbl = (const float*)d_in[7];
    const float* fWr = (const float*)d_in[8];
    const float* c1w = (const float*)d_in[9];
    const float* c2w = (const float*)d_in[10];
    const float* fcw = (const float*)d_in[11];
    const float* fcb = (const float*)d_in[12];

    prep_all<<<1 + (SEQ * SEQ) / 256, 256>>>(gei, fei, Wl, bl, Wr, c1w, c2w, fcw, fcb, fWl, fWr);
    dim3 grid(CAP, BZ);
    stconv_kernel<<<grid, NTHR>>>(src, fbl, (float*)d_out);
}

// round 9
// speedup vs baseline: 1.1690x; 1.0148x over previous
#include <cuda_runtime.h>

#define BZ   32
#define CAP  134
#define SEQ  144
#define INV  16
#define E_SP 1072
#define E_FT 64
#define NTHR 160
#define XSTR 152   // 2 zero guard cols + 144 + pad (sX row stride)
#define SOFF 2     // guard offset
#define YSTR 20    // padded row stride for sYA/sYF

// ---------------- device-global precomputed state (no cudaMalloc allowed) ----
__device__ int    g_rowptr[CAP + 1];
__device__ int    g_col[E_SP];
__device__ float  g_invdeg[CAP];
__device__ float  g_G1[INV][INV];   // Wl @ F1
__device__ float  g_G2[INV][INV];   // Wr @ F1
__device__ float  g_B1[INV][INV];   // A^T @ F2
__device__ float  g_F2[INV][INV];   // F2
__device__ float  g_V[5][INV][INV]; // combined conv taps folded with F3
__device__ float  g_csF2[INV];      // column sums of F2 (for fgcn_bl term)
__device__ float  g_const[INV];     // bl@F1 + fc_b
__device__ float2 g_W2[SEQ * SEQ];  // packed (fWl[t][s], fWr[t][s])

// ---------------- fused prep: block 0 = CSR + folded matrices (all smem),
// ---------------- blocks 1..81 = W2 packing (81*256 == SEQ*SEQ) -------------
__global__ void prep_all(const int* __restrict__ gei, const int* __restrict__ fei,
                         const float* __restrict__ Wl, const float* __restrict__ bl,
                         const float* __restrict__ Wr,
                         const float* __restrict__ c1w, const float* __restrict__ c2w,
                         const float* __restrict__ fcw, const float* __restrict__ fcb,
                         const float* __restrict__ fWl, const float* __restrict__ fWr) {
    const int tid = threadIdx.x;   // 256 threads
    const int bx  = blockIdx.x;

    if (bx > 0) {
        int i = (bx - 1) * 256 + tid;   // exactly covers SEQ*SEQ = 20736
        g_W2[i] = make_float2(fWl[i], fWr[i]);
        return;
    }

    __shared__ int   s_src[E_SP];
    __shared__ int   s_dst[E_SP];
    __shared__ int   s_deg[CAP];
    __shared__ int   sc_a[256], sc_b[256];
    __shared__ int   s_fe[2 * E_FT];
    __shared__ int   s_cnt[INV][INV];
    __shared__ float s_A[INV][INV];
    __shared__ float s_fcw[48 * INV];
    __shared__ float s_Wl[INV * INV], s_Wr[INV * INV], s_bl[INV], s_fcb[INV];
    __shared__ float s_c1[INV * INV * 3], s_c2[INV * INV * 5];

    for (int e = tid; e < E_SP; e += 256) { s_src[e] = gei[e]; s_dst[e] = gei[E_SP + e]; }
    for (int i = tid; i < 2 * E_FT; i += 256) s_fe[i] = fei[i];
    for (int i = tid; i < 48 * INV; i += 256) s_fcw[i] = fcw[i];
    for (int i = tid; i < INV * INV; i += 256) { s_Wl[i] = Wl[i]; s_Wr[i] = Wr[i]; }
    for (int i = tid; i < INV * INV * 3; i += 256) s_c1[i] = c1w[i];
    for (int i = tid; i < INV * INV * 5; i += 256) s_c2[i] = c2w[i];
    if (tid < INV) { s_bl[tid] = bl[tid]; s_fcb[tid] = fcb[tid]; }
    if (tid < CAP) s_deg[tid] = 0;
    __syncthreads();

    for (int e = tid; e < E_SP; e += 256) atomicAdd(&s_deg[s_dst[e]], 1);
    __syncthreads();

    int v = (tid < CAP) ? s_deg[tid] : 0;
    sc_a[tid] = v;
    __syncthreads();
    int* cur = sc_a; int* nxt = sc_b;
    #pragma unroll
    for (int off = 1; off < 256; off <<= 1) {
        int x = cur[tid];
        if (tid >= off) x += cur[tid - off];
        nxt[tid] = x;
        __syncthreads();
        int* t = cur; cur = nxt; nxt = t;
    }
    int incl = cur[tid];
    int excl = incl - v;
    if (tid < CAP) {
        g_rowptr[tid] = excl;
        g_invdeg[tid] = 1.0f / fmaxf((float)v, 1.0f);
        if (tid == CAP - 1) g_rowptr[CAP] = incl;
    }

    if (tid < CAP) {
        int k = excl;
        #pragma unroll 8
        for (int e = 0; e < E_SP; e++)
            if (s_dst[e] == tid) g_col[k++] = s_src[e];
    }

    {
        int i = tid >> 4, j = tid & 15;
        int cnt = 0;
        #pragma unroll
        for (int e = 0; e < E_FT; e++)
            if (s_fe[E_FT + e] == i && s_fe[e] == j) cnt++;
        s_cnt[i][j] = cnt;
    }
    __syncthreads();
    {
        int i = tid >> 4, j = tid & 15;
        int dsum = 0;
        #pragma unroll
        for (int jj = 0; jj < INV; jj++) dsum += s_cnt[i][jj];
        s_A[i][j] = (float)s_cnt[i][j] / fmaxf((float)dsum, 1.0f);
    }
    __syncthreads();

    {
        int r = tid >> 4, o = tid & 15;
        float g1 = 0.f, g2 = 0.f, b1 = 0.f;
        #pragma unroll
        for (int i = 0; i < INV; i++) {
            float f1 = s_fcw[i * INV + o];
            float f2 = s_fcw[(INV + i) * INV + o];
            g1 += s_Wl[r * INV + i] * f1;
            g2 += s_Wr[r * INV + i] * f1;
            b1 += s_A[i][r] * f2;
        }
        g_G1[r][o] = g1; g_G2[r][o] = g2; g_B1[r][o] = b1;
        g_F2[r][o] = s_fcw[(INV + r) * INV + o];
        #pragma unroll
        for (int k = 0; k < 5; k++) {
            float vv = 0.f;
            #pragma unroll
            for (int o2 = 0; o2 < INV; o2++) {
                float w5 = s_c2[(o2 * INV + r) * 5 + k];
                if (k >= 1 && k <= 3) w5 += s_c1[(o2 * INV + r) * 3 + (k - 1)];
                vv += w5 * s_fcw[(32 + o2) * INV + o];
            }
            g_V[k][r][o] = vv;
        }
        if (r == 0) {
            float cs = 0.f, cv = 0.f;
            #pragma unroll
            for (int i = 0; i < INV; i++) {
                cs += s_fcw[(INV + i) * INV + o];
                cv += s_bl[i] * s_fcw[i * INV + o];
            }
            g_csF2[o] = cs;
            g_const[o] = cv + s_fcb[o];
        }
    }
}

// FMA helpers on float4 accumulators
__device__ __forceinline__ void fma4(float4& a, float s, const float4 m) {
    a.x += s * m.x; a.y += s * m.y; a.z += s * m.z; a.w += s * m.w;
}

// ---------------- main fused kernel: one (b,c) slice per block --------------
__global__ __launch_bounds__(NTHR, 5)
void stconv_kernel(const float* __restrict__ src,
                   const float* __restrict__ fbl,
                   float* __restrict__ out) {
    __shared__ __align__(16) float sX[INV][XSTR];      // transposed X with 2 zero guard cols
    __shared__ __align__(16) float sYA[SEQ][YSTR];     // X @ (A^T F2)
    __shared__ __align__(16) float sYF[SEQ][YSTR];     // X @ F2
    __shared__ __align__(16) float sG1[INV][INV], sG2[INV][INV], sB1[INV][INV], sF2[INV][INV];
    __shared__ __align__(16) float sV[5][INV][INV];
    __shared__ float sCs[INV], sC0[INV];

    const int c = blockIdx.x, b = blockIdx.y;
    const int tid = threadIdx.x;
    const int s = tid;
    const int base = ((b * CAP + c) * SEQ) * INV;

    // copy folded matrices; zero guard columns of sX
    for (int idx = tid; idx < INV * INV; idx += NTHR) {
        int r = idx >> 4, o = idx & 15;
        sG1[r][o] = g_G1[r][o]; sG2[r][o] = g_G2[r][o];
        sB1[r][o] = g_B1[r][o]; sF2[r][o] = g_F2[r][o];
        #pragma unroll
        for (int k = 0; k < 5; k++) sV[k][r][o] = g_V[k][r][o];
        if (r == 0) { sCs[o] = g_csF2[o]; sC0[o] = g_const[o]; }
    }
    if (tid < 2 * INV) {            // zero left guard cols 0,1 for all 16 rows
        sX[tid >> 1][tid & 1] = 0.f;
    } else if (tid < 2 * INV + (XSTR - SEQ - SOFF) * INV) {  // right cols [146,152)
        int q = tid - 2 * INV;
        sX[q % INV][SEQ + SOFF + q / INV] = 0.f;
    }

    if (s < SEQ) {
        const float4* p = (const float4*)(src + base + s * INV);
        float4 a0 = p[0], a1 = p[1], a2 = p[2], a3 = p[3];
        int ss = s + SOFF;
        sX[0][ss]=a0.x;  sX[1][ss]=a0.y;  sX[2][ss]=a0.z;  sX[3][ss]=a0.w;
        sX[4][ss]=a1.x;  sX[5][ss]=a1.y;  sX[6][ss]=a1.z;  sX[7][ss]=a1.w;
        sX[8][ss]=a2.x;  sX[9][ss]=a2.y;  sX[10][ss]=a2.z; sX[11][ss]=a2.w;
        sX[12][ss]=a3.x; sX[13][ss]=a3.y; sX[14][ss]=a3.z; sX[15][ss]=a3.w;
    }
    __syncthreads();

    float4 ac0, ac1, ac2, ac3;
    if (s < SEQ) {
        const int ss = s + SOFF;

        // YA = X @ B1, YF = X @ F2 (row s) -> smem, explicit float4 LDS
        {
            float4 ya0 = {0,0,0,0}, ya1 = {0,0,0,0}, ya2 = {0,0,0,0}, ya3 = {0,0,0,0};
            float4 yf0 = {0,0,0,0}, yf1 = {0,0,0,0}, yf2 = {0,0,0,0}, yf3 = {0,0,0,0};
            #pragma unroll
            for (int j = 0; j < 16; j++) {
                float xv = sX[j][ss];
                const float4* br = (const float4*)sB1[j];
                const float4* fr = (const float4*)sF2[j];
                fma4(ya0, xv, br[0]); fma4(ya1, xv, br[1]);
                fma4(ya2, xv, br[2]); fma4(ya3, xv, br[3]);
                fma4(yf0, xv, fr[0]); fma4(yf1, xv, fr[1]);
                fma4(yf2, xv, fr[2]); fma4(yf3, xv, fr[3]);
            }
            float4* yaw = (float4*)sYA[s];
            float4* yfw = (float4*)sYF[s];
            yaw[0] = ya0; yaw[1] = ya1; yaw[2] = ya2; yaw[3] = ya3;
            yfw[0] = yf0; yfw[1] = yf1; yfw[2] = yf2; yfw[3] = yf3;
        }

        // constant + fgcn_bl term
        {
            float fblv = __ldg(fbl + s);
            const float4* c0 = (const float4*)sC0;
            const float4* cs4 = (const float4*)sCs;
            ac0 = c0[0]; fma4(ac0, fblv, cs4[0]);
            ac1 = c0[1]; fma4(ac1, fblv, cs4[1]);
            ac2 = c0[2]; fma4(ac2, fblv, cs4[2]);
            ac3 = c0[3]; fma4(ac3, fblv, cs4[3]);
        }

        // spatial: gather mean over graph neighbors of c
        {
            int r0 = g_rowptr[c], r1 = g_rowptr[c + 1];
            float4 m0 = {0,0,0,0}, m1 = {0,0,0,0}, m2 = {0,0,0,0}, m3 = {0,0,0,0};
            for (int e = r0; e < r1; e++) {
                int nb = g_col[e];
                const float4* p = (const float4*)(src + ((b * CAP + nb) * SEQ + s) * INV);
                float4 a0 = __ldg(p), a1 = __ldg(p + 1), a2 = __ldg(p + 2), a3 = __ldg(p + 3);
                m0.x+=a0.x; m0.y+=a0.y; m0.z+=a0.z; m0.w+=a0.w;
                m1.x+=a1.x; m1.y+=a1.y; m1.z+=a1.z; m1.w+=a1.w;
                m2.x+=a2.x; m2.y+=a2.y; m2.z+=a2.z; m2.w+=a2.w;
                m3.x+=a3.x; m3.y+=a3.y; m3.z+=a3.z; m3.w+=a3.w;
            }
            float sc = g_invdeg[c];
            float mg[16] = {m0.x*sc,m0.y*sc,m0.z*sc,m0.w*sc, m1.x*sc,m1.y*sc,m1.z*sc,m1.w*sc,
                            m2.x*sc,m2.y*sc,m2.z*sc,m2.w*sc, m3.x*sc,m3.y*sc,m3.z*sc,m3.w*sc};
            #pragma unroll
            for (int j = 0; j < 16; j++) {
                float m = mg[j];
                float xv = sX[j][ss];
                const float4* g1r = (const float4*)sG1[j];
                const float4* g2r = (const float4*)sG2[j];
                fma4(ac0, m, g1r[0]); fma4(ac1, m, g1r[1]);
                fma4(ac2, m, g1r[2]); fma4(ac3, m, g1r[3]);
                fma4(ac0, xv, g2r[0]); fma4(ac1, xv, g2r[1]);
                fma4(ac2, xv, g2r[2]); fma4(ac3, xv, g2r[3]);
            }
        }

        // temporal: branchless 5-tap conv (guard cols are zero)
        #pragma unroll
        for (int k = 0; k < 5; k++) {
            const int sp = ss + k - 2;
            #pragma unroll
            for (int j = 0; j < 16; j++) {
                float xv = sX[j][sp];
                const float4* vr = (const float4*)sV[k][j];
                fma4(ac0, xv, vr[0]); fma4(ac1, xv, vr[1]);
                fma4(ac2, xv, vr[2]); fma4(ac3, xv, vr[3]);
            }
        }
    }
    __syncthreads();

    if (s < SEQ) {
        // big GEMM: acc += sum_t fWl[t][s]*YA[t][:] + fWr[t][s]*YF[t][:]
        const float2* wp = g_W2 + s;
        #pragma unroll 4
        for (int t = 0; t < SEQ; t++) {
            float2 w = __ldg(wp + t * SEQ);
            float a = w.x, bb = w.y;
            const float4* yap = (const float4*)sYA[t];
            const float4* yfp = (const float4*)sYF[t];
            float4 u0 = yap[0], u1 = yap[1], u2 = yap[2], u3 = yap[3];
            float4 v0 = yfp[0], v1 = yfp[1], v2 = yfp[2], v3 = yfp[3];
            fma4(ac0, a, u0); fma4(ac0, bb, v0);
            fma4(ac1, a, u1); fma4(ac1, bb, v1);
            fma4(ac2, a, u2); fma4(ac2, bb, v2);
            fma4(ac3, a, u3); fma4(ac3, bb, v3);
        }

        // out = src + contributions (x re-read from smem)
        const int ss = s + SOFF;
        float4* po = (float4*)(out + base + s * INV);
        po[0] = make_float4(sX[0][ss]+ac0.x,  sX[1][ss]+ac0.y,  sX[2][ss]+ac0.z,  sX[3][ss]+ac0.w);
        po[1] = make_float4(sX[4][ss]+ac1.x,  sX[5][ss]+ac1.y,  sX[6][ss]+ac1.z,  sX[7][ss]+ac1.w);
        po[2] = make_float4(sX[8][ss]+ac2.x,  sX[9][ss]+ac2.y,  sX[10][ss]+ac2.z, sX[11][ss]+ac2.w);
        po[3] = make_float4(sX[12][ss]+ac3.x, sX[13][ss]+ac3.y, sX[14][ss]+ac3.z, sX[15][ss]+ac3.w);
    }
}

// ---------------- launch ----------------------------------------------------
extern "C" void kernel_launch(void* const* d_in, const int* in_sizes, int n_in,
                              void* d_out, int out_size) {
    const float* src = (const float*)d_in[0];
    const int*   gei = (const int*)d_in[1];
    const int*   fei = (const int*)d_in[2];
    const float* Wl  = (const float*)d_in[3];
    const float* bl  = (const float*)d_in[4];
    const float* Wr  = (const float*)d_in[5];
    const float* fWl = (const float*)d_in[6];
    const float* fbl = (const float*)d_in[7];
    const float* fWr = (const float*)d_in[8];
    const float* c1w = (const float*)d_in[9];
    const float* c2w = (const float*)d_in[10];
    const float* fcw = (const float*)d_in[11];
    const float* fcb = (const float*)d_in[12];

    prep_all<<<1 + (SEQ * SEQ) / 256, 256>>>(gei, fei, Wl, bl, Wr, c1w, c2w, fcw, fcb, fWl, fWr);
    dim3 grid(CAP, BZ);
    stconv_kernel<<<grid, NTHR>>>(src, fbl, (float*)d_out);
}

// round 10
// speedup vs baseline: 1.5080x; 1.2900x over previous
#include <cuda_runtime.h>

#define BZ   32
#define CAP  134
#define SEQ  144
#define INV  16
#define E_SP 1072
#define E_FT 64
#define NTHR 160
#define XSTR 152   // 2 zero guard cols + 144 + pad (sX row stride)
#define SOFF 2     // guard offset
#define YSTR 20    // padded row stride for sYA/sYF

// ---------------- device-global precomputed state (no cudaMalloc allowed) ----
__device__ int    g_rowptr[CAP + 1];
__device__ int    g_col[E_SP];
__device__ float  g_invdeg[CAP];
__device__ float  g_G1[INV][INV];   // Wl @ F1
__device__ float  g_G2[INV][INV];   // Wr @ F1
__device__ float  g_B1[INV][INV];   // A^T @ F2
__device__ float  g_F2[INV][INV];   // F2
__device__ float  g_V[5][INV][INV]; // combined conv taps folded with F3
__device__ float  g_csF2[INV];      // column sums of F2 (for fgcn_bl term)
__device__ float  g_const[INV];     // bl@F1 + fc_b
__device__ float2 g_W2[SEQ * SEQ];  // packed (fWl[t][s], fWr[t][s])

// ---------------- fused prep: block 0 = CSR + folded matrices (all smem),
// ---------------- blocks 1..81 = W2 packing (81*256 == SEQ*SEQ) -------------
__global__ void prep_all(const int* __restrict__ gei, const int* __restrict__ fei,
                         const float* __restrict__ Wl, const float* __restrict__ bl,
                         const float* __restrict__ Wr,
                         const float* __restrict__ c1w, const float* __restrict__ c2w,
                         const float* __restrict__ fcw, const float* __restrict__ fcb,
                         const float* __restrict__ fWl, const float* __restrict__ fWr) {
    const int tid = threadIdx.x;   // 256 threads
    const int bx  = blockIdx.x;

    if (bx > 0) {
        int i = (bx - 1) * 256 + tid;   // exactly covers SEQ*SEQ = 20736
        g_W2[i] = make_float2(fWl[i], fWr[i]);
        return;
    }

    __shared__ int   s_src[E_SP];
    __shared__ int   s_dst[E_SP];
    __shared__ int   s_deg[CAP];
    __shared__ int   sc_a[256], sc_b[256];
    __shared__ int   s_fe[2 * E_FT];
    __shared__ int   s_cnt[INV][INV];
    __shared__ float s_A[INV][INV];
    __shared__ float s_fcw[48 * INV];
    __shared__ float s_Wl[INV * INV], s_Wr[INV * INV], s_bl[INV], s_fcb[INV];
    __shared__ float s_c1[INV * INV * 3], s_c2[INV * INV * 5];

    for (int e = tid; e < E_SP; e += 256) { s_src[e] = gei[e]; s_dst[e] = gei[E_SP + e]; }
    for (int i = tid; i < 2 * E_FT; i += 256) s_fe[i] = fei[i];
    for (int i = tid; i < 48 * INV; i += 256) s_fcw[i] = fcw[i];
    for (int i = tid; i < INV * INV; i += 256) { s_Wl[i] = Wl[i]; s_Wr[i] = Wr[i]; }
    for (int i = tid; i < INV * INV * 3; i += 256) s_c1[i] = c1w[i];
    for (int i = tid; i < INV * INV * 5; i += 256) s_c2[i] = c2w[i];
    if (tid < INV) { s_bl[tid] = bl[tid]; s_fcb[tid] = fcb[tid]; }
    if (tid < CAP) s_deg[tid] = 0;
    __syncthreads();

    for (int e = tid; e < E_SP; e += 256) atomicAdd(&s_deg[s_dst[e]], 1);
    __syncthreads();

    int v = (tid < CAP) ? s_deg[tid] : 0;
    sc_a[tid] = v;
    __syncthreads();
    int* cur = sc_a; int* nxt = sc_b;
    #pragma unroll
    for (int off = 1; off < 256; off <<= 1) {
        int x = cur[tid];
        if (tid >= off) x += cur[tid - off];
        nxt[tid] = x;
        __syncthreads();
        int* t = cur; cur = nxt; nxt = t;
    }
    int incl = cur[tid];
    int excl = incl - v;
    if (tid < CAP) {
        g_rowptr[tid] = excl;
        g_invdeg[tid] = 1.0f / fmaxf((float)v, 1.0f);
        if (tid == CAP - 1) g_rowptr[CAP] = incl;
    }

    if (tid < CAP) {
        int k = excl;
        #pragma unroll 8
        for (int e = 0; e < E_SP; e++)
            if (s_dst[e] == tid) g_col[k++] = s_src[e];
    }

    {
        int i = tid >> 4, j = tid & 15;
        int cnt = 0;
        #pragma unroll
        for (int e = 0; e < E_FT; e++)
            if (s_fe[E_FT + e] == i && s_fe[e] == j) cnt++;
        s_cnt[i][j] = cnt;
    }
    __syncthreads();
    {
        int i = tid >> 4, j = tid & 15;
        int dsum = 0;
        #pragma unroll
        for (int jj = 0; jj < INV; jj++) dsum += s_cnt[i][jj];
        s_A[i][j] = (float)s_cnt[i][j] / fmaxf((float)dsum, 1.0f);
    }
    __syncthreads();

    {
        int r = tid >> 4, o = tid & 15;
        float g1 = 0.f, g2 = 0.f, b1 = 0.f;
        #pragma unroll
        for (int i = 0; i < INV; i++) {
            float f1 = s_fcw[i * INV + o];
            float f2 = s_fcw[(INV + i) * INV + o];
            g1 += s_Wl[r * INV + i] * f1;
            g2 += s_Wr[r * INV + i] * f1;
            b1 += s_A[i][r] * f2;
        }
        g_G1[r][o] = g1; g_G2[r][o] = g2; g_B1[r][o] = b1;
        g_F2[r][o] = s_fcw[(INV + r) * INV + o];
        #pragma unroll
        for (int k = 0; k < 5; k++) {
            float vv = 0.f;
            #pragma unroll
            for (int o2 = 0; o2 < INV; o2++) {
                float w5 = s_c2[(o2 * INV + r) * 5 + k];
                if (k >= 1 && k <= 3) w5 += s_c1[(o2 * INV + r) * 3 + (k - 1)];
                vv += w5 * s_fcw[(32 + o2) * INV + o];
            }
            g_V[k][r][o] = vv;
        }
        if (r == 0) {
            float cs = 0.f, cv = 0.f;
            #pragma unroll
            for (int i = 0; i < INV; i++) {
                cs += s_fcw[(INV + i) * INV + o];
                cv += s_bl[i] * s_fcw[i * INV + o];
            }
            g_csF2[o] = cs;
            g_const[o] = cv + s_fcb[o];
        }
    }
}

// FMA helper on float4 accumulators
__device__ __forceinline__ void fma4(float4& a, float s, const float4 m) {
    a.x += s * m.x; a.y += s * m.y; a.z += s * m.z; a.w += s * m.w;
}

// ---------------- main fused kernel: one (b,c) slice per block --------------
// 160 threads; tid<144 active: sp = tid>>1 (s-pair base), h = tid&1 (output half).
// Each thread owns s ∈ {sp, sp+72} x channels [8h, 8h+8) -> 0.5 FMA/smem-byte.
__global__ __launch_bounds__(NTHR, 5)
void stconv_kernel(const float* __restrict__ src,
                   const float* __restrict__ fbl,
                   float* __restrict__ out) {
    __shared__ __align__(16) float sX[INV][XSTR];      // transposed X with zero guard cols
    __shared__ __align__(16) float sYA[SEQ][YSTR];     // X @ (A^T F2)
    __shared__ __align__(16) float sYF[SEQ][YSTR];     // X @ F2
    __shared__ __align__(16) float sG1[INV][INV], sG2[INV][INV], sB1[INV][INV], sF2[INV][INV];
    __shared__ __align__(16) float sV[5][INV][INV];
    __shared__ __align__(16) float sCs[INV], sC0[INV];

    const int c = blockIdx.x, b = blockIdx.y;
    const int tid = threadIdx.x;
    const bool act = tid < 144;
    const int sp = tid >> 1;    // 0..71
    const int h  = tid & 1;
    const int q  = 2 * h;       // float4 index of this thread's channel half
    const int base = ((b * CAP + c) * SEQ) * INV;

    // copy folded matrices
    for (int idx = tid; idx < INV * INV; idx += NTHR) {
        int r = idx >> 4, o = idx & 15;
        sG1[r][o] = g_G1[r][o]; sG2[r][o] = g_G2[r][o];
        sB1[r][o] = g_B1[r][o]; sF2[r][o] = g_F2[r][o];
        #pragma unroll
        for (int k = 0; k < 5; k++) sV[k][r][o] = g_V[k][r][o];
        if (r == 0) { sCs[o] = g_csF2[o]; sC0[o] = g_const[o]; }
    }
    // zero guard columns of sX: left cols {0,1}, right cols [146,152)
    if (tid < 2 * INV) {
        sX[tid >> 1][tid & 1] = 0.f;
    } else if (tid < 2 * INV + (XSTR - SEQ - SOFF) * INV) {
        int g = tid - 2 * INV;
        sX[g % INV][SEQ + SOFF + g / INV] = 0.f;
    }

    // X load: thread tid loads row s=tid (transposed into sX)
    if (act) {
        const float4* p = (const float4*)(src + base + tid * INV);
        float4 a0 = p[0], a1 = p[1], a2 = p[2], a3 = p[3];
        int ss = tid + SOFF;
        sX[0][ss]=a0.x;  sX[1][ss]=a0.y;  sX[2][ss]=a0.z;  sX[3][ss]=a0.w;
        sX[4][ss]=a1.x;  sX[5][ss]=a1.y;  sX[6][ss]=a1.z;  sX[7][ss]=a1.w;
        sX[8][ss]=a2.x;  sX[9][ss]=a2.y;  sX[10][ss]=a2.z; sX[11][ss]=a2.w;
        sX[12][ss]=a3.x; sX[13][ss]=a3.y; sX[14][ss]=a3.z; sX[15][ss]=a3.w;
    }
    __syncthreads();

    float4 acc[2][2];   // [m][lo/hi float4 of this thread's 8 channels]
    if (act) {
        const int r0 = g_rowptr[c], r1 = g_rowptr[c + 1];
        const float sc = g_invdeg[c];

        #pragma unroll
        for (int m = 0; m < 2; m++) {
            const int s  = sp + 72 * m;
            const int ss = s + SOFF;

            // YA/YF half-row for (s, h)
            {
                float4 ya0 = {0,0,0,0}, ya1 = {0,0,0,0};
                float4 yf0 = {0,0,0,0}, yf1 = {0,0,0,0};
                #pragma unroll
                for (int j = 0; j < 16; j++) {
                    float xv = sX[j][ss];
                    const float4* br = (const float4*)sB1[j];
                    const float4* fr = (const float4*)sF2[j];
                    fma4(ya0, xv, br[q]); fma4(ya1, xv, br[q + 1]);
                    fma4(yf0, xv, fr[q]); fma4(yf1, xv, fr[q + 1]);
                }
                float4* yaw = (float4*)sYA[s];
                float4* yfw = (float4*)sYF[s];
                yaw[q] = ya0; yaw[q + 1] = ya1;
                yfw[q] = yf0; yfw[q + 1] = yf1;
            }

            // constant + fgcn_bl term
            {
                float fblv = __ldg(fbl + s);
                acc[m][0] = ((const float4*)sC0)[q];
                acc[m][1] = ((const float4*)sC0)[q + 1];
                fma4(acc[m][0], fblv, ((const float4*)sCs)[q]);
                fma4(acc[m][1], fblv, ((const float4*)sCs)[q + 1]);
            }

            // spatial: gather mean over graph neighbors of c (full 16 channels)
            {
                float4 m0 = {0,0,0,0}, m1 = {0,0,0,0}, m2 = {0,0,0,0}, m3 = {0,0,0,0};
                for (int e = r0; e < r1; e++) {
                    int nb = g_col[e];
                    const float4* p = (const float4*)(src + ((b * CAP + nb) * SEQ + s) * INV);
                    float4 a0 = __ldg(p), a1 = __ldg(p + 1), a2 = __ldg(p + 2), a3 = __ldg(p + 3);
                    m0.x+=a0.x; m0.y+=a0.y; m0.z+=a0.z; m0.w+=a0.w;
                    m1.x+=a1.x; m1.y+=a1.y; m1.z+=a1.z; m1.w+=a1.w;
                    m2.x+=a2.x; m2.y+=a2.y; m2.z+=a2.z; m2.w+=a2.w;
                    m3.x+=a3.x; m3.y+=a3.y; m3.z+=a3.z; m3.w+=a3.w;
                }
                float mg[16] = {m0.x*sc,m0.y*sc,m0.z*sc,m0.w*sc, m1.x*sc,m1.y*sc,m1.z*sc,m1.w*sc,
                                m2.x*sc,m2.y*sc,m2.z*sc,m2.w*sc, m3.x*sc,m3.y*sc,m3.z*sc,m3.w*sc};
                #pragma unroll
                for (int j = 0; j < 16; j++) {
                    float mm = mg[j];
                    float xv = sX[j][ss];
                    const float4* g1r = (const float4*)sG1[j];
                    const float4* g2r = (const float4*)sG2[j];
                    fma4(acc[m][0], mm, g1r[q]); fma4(acc[m][1], mm, g1r[q + 1]);
                    fma4(acc[m][0], xv, g2r[q]); fma4(acc[m][1], xv, g2r[q + 1]);
                }
            }
        }

        // temporal: merged over the two s-positions (V rows loaded once)
        {
            const int ss0 = sp + SOFF, ss1 = sp + 72 + SOFF;
            #pragma unroll
            for (int k = 0; k < 5; k++) {
                #pragma unroll
                for (int j = 0; j < 16; j++) {
                    const float4* vr = (const float4*)sV[k][j];
                    float4 v0 = vr[q], v1 = vr[q + 1];
                    float x0 = sX[j][ss0 + k - 2];
                    float x1 = sX[j][ss1 + k - 2];
                    fma4(acc[0][0], x0, v0); fma4(acc[0][1], x0, v1);
                    fma4(acc[1][0], x1, v0); fma4(acc[1][1], x1, v1);
                }
            }
        }
    }
    __syncthreads();

    if (act) {
        // big GEMM: both s-positions share each Y row read -> 0.5 FMA/byte
        const int s0 = sp, s1 = sp + 72;
        const float2* wp = g_W2;
        #pragma unroll 4
        for (int t = 0; t < SEQ; t++) {
            float2 wA = __ldg(wp + t * SEQ + s0);
            float2 wB = __ldg(wp + t * SEQ + s1);
            const float4* yap = (const float4*)sYA[t];
            const float4* yfp = (const float4*)sYF[t];
            float4 u0 = yap[q], u1 = yap[q + 1];
            float4 v0 = yfp[q], v1 = yfp[q + 1];
            fma4(acc[0][0], wA.x, u0); fma4(acc[0][0], wA.y, v0);
            fma4(acc[0][1], wA.x, u1); fma4(acc[0][1], wA.y, v1);
            fma4(acc[1][0], wB.x, u0); fma4(acc[1][0], wB.y, v0);
            fma4(acc[1][1], wB.x, u1); fma4(acc[1][1], wB.y, v1);
        }

        // out = src + contributions (x re-read from smem), 8 channels per s
        #pragma unroll
        for (int m = 0; m < 2; m++) {
            const int s  = sp + 72 * m;
            const int ss = s + SOFF;
            const int ob = 8 * h;
            float4* po = (float4*)(out + base + s * INV);
            po[q]     = make_float4(sX[ob+0][ss]+acc[m][0].x, sX[ob+1][ss]+acc[m][0].y,
                                    sX[ob+2][ss]+acc[m][0].z, sX[ob+3][ss]+acc[m][0].w);
            po[q + 1] = make_float4(sX[ob+4][ss]+acc[m][1].x, sX[ob+5][ss]+acc[m][1].y,
                                    sX[ob+6][ss]+acc[m][1].z, sX[ob+7][ss]+acc[m][1].w);
        }
    }
}

// ---------------- launch ----------------------------------------------------
extern "C" void kernel_launch(void* const* d_in, const int* in_sizes, int n_in,
                              void* d_out, int out_size) {
    const float* src = (const float*)d_in[0];
    const int*   gei = (const int*)d_in[1];
    const int*   fei = (const int*)d_in[2];
    const float* Wl  = (const float*)d_in[3];
    const float* bl  = (const float*)d_in[4];
    const float* Wr  = (const float*)d_in[5];
    const float* fWl = (const float*)d_in[6];
    const float* fbl = (const float*)d_in[7];
    const float* fWr = (const float*)d_in[8];
    const float* c1w = (const float*)d_in[9];
    const float* c2w = (const float*)d_in[10];
    const float* fcw = (const float*)d_in[11];
    const float* fcb = (const float*)d_in[12];

    prep_all<<<1 + (SEQ * SEQ) / 256, 256>>>(gei, fei, Wl, bl, Wr, c1w, c2w, fcw, fcb, fWl, fWr);
    dim3 grid(CAP, BZ);
    stconv_kernel<<<grid, NTHR>>>(src, fbl, (float*)d_out);
}

// round 11
// speedup vs baseline: 1.6951x; 1.1241x over previous
#include <cuda_runtime.h>

#define BZ   32
#define CAP  134
#define SEQ  144
#define INV  16
#define E_SP 1072
#define E_FT 64
#define NTHR 160
#define XSTR 152   // 2 zero guard cols + 144 + pad (sX row stride)
#define SOFF 2     // guard offset
#define YSTR 20    // padded row stride for sYA/sYF (80B rows, 16B-aligned)

typedef unsigned long long u64;

// ---------------- f32x2 packed helpers (sm_103a) -----------------------------
__device__ __forceinline__ u64 pack2(float x, float y) {
    u64 r; asm("mov.b64 %0, {%1, %2};" : "=l"(r) : "f"(x), "f"(y)); return r;
}
__device__ __forceinline__ u64 splat2(float x) { return pack2(x, x); }
__device__ __forceinline__ u64 ffma2(u64 a, u64 b, u64 c) {
    u64 d; asm("fma.rn.f32x2 %0, %1, %2, %3;" : "=l"(d) : "l"(a), "l"(b), "l"(c)); return d;
}
__device__ __forceinline__ u64 add2(u64 a, u64 b) {
    u64 d; asm("add.rn.f32x2 %0, %1, %2;" : "=l"(d) : "l"(a), "l"(b)); return d;
}

// ---------------- device-global precomputed state (no cudaMalloc allowed) ----
__device__ int    g_rowptr[CAP + 1];
__device__ int    g_col[E_SP];
__device__ float  g_invdeg[CAP];
__device__ float  g_G1[INV][INV];   // Wl @ F1
__device__ float  g_G2[INV][INV];   // Wr @ F1
__device__ float  g_B1[INV][INV];   // A^T @ F2
__device__ float  g_F2[INV][INV];   // F2
__device__ float  g_V[5][INV][INV]; // combined conv taps folded with F3
__device__ float  g_csF2[INV];      // column sums of F2 (for fgcn_bl term)
__device__ float  g_const[INV];     // bl@F1 + fc_b
__device__ float2 g_W2[SEQ * SEQ];  // packed (fWl[t][s], fWr[t][s])

// ---------------- fused prep: block 0 = CSR + folded matrices (all smem),
// ---------------- blocks 1..81 = W2 packing (81*256 == SEQ*SEQ) -------------
__global__ void prep_all(const int* __restrict__ gei, const int* __restrict__ fei,
                         const float* __restrict__ Wl, const float* __restrict__ bl,
                         const float* __restrict__ Wr,
                         const float* __restrict__ c1w, const float* __restrict__ c2w,
                         const float* __restrict__ fcw, const float* __restrict__ fcb,
                         const float* __restrict__ fWl, const float* __restrict__ fWr) {
    const int tid = threadIdx.x;   // 256 threads
    const int bx  = blockIdx.x;

    if (bx > 0) {
        int i = (bx - 1) * 256 + tid;
        g_W2[i] = make_float2(fWl[i], fWr[i]);
        return;
    }

    __shared__ int   s_src[E_SP];
    __shared__ int   s_dst[E_SP];
    __shared__ int   s_deg[CAP];
    __shared__ int   sc_a[256], sc_b[256];
    __shared__ int   s_fe[2 * E_FT];
    __shared__ int   s_cnt[INV][INV];
    __shared__ float s_A[INV][INV];
    __shared__ float s_fcw[48 * INV];
    __shared__ float s_Wl[INV * INV], s_Wr[INV * INV], s_bl[INV], s_fcb[INV];
    __shared__ float s_c1[INV * INV * 3], s_c2[INV * INV * 5];

    for (int e = tid; e < E_SP; e += 256) { s_src[e] = gei[e]; s_dst[e] = gei[E_SP + e]; }
    for (int i = tid; i < 2 * E_FT; i += 256) s_fe[i] = fei[i];
    for (int i = tid; i < 48 * INV; i += 256) s_fcw[i] = fcw[i];
    for (int i = tid; i < INV * INV; i += 256) { s_Wl[i] = Wl[i]; s_Wr[i] = Wr[i]; }
    for (int i = tid; i < INV * INV * 3; i += 256) s_c1[i] = c1w[i];
    for (int i = tid; i < INV * INV * 5; i += 256) s_c2[i] = c2w[i];
    if (tid < INV) { s_bl[tid] = bl[tid]; s_fcb[tid] = fcb[tid]; }
    if (tid < CAP) s_deg[tid] = 0;
    __syncthreads();

    for (int e = tid; e < E_SP; e += 256) atomicAdd(&s_deg[s_dst[e]], 1);
    __syncthreads();

    int v = (tid < CAP) ? s_deg[tid] : 0;
    sc_a[tid] = v;
    __syncthreads();
    int* cur = sc_a; int* nxt = sc_b;
    #pragma unroll
    for (int off = 1; off < 256; off <<= 1) {
        int x = cur[tid];
        if (tid >= off) x += cur[tid - off];
        nxt[tid] = x;
        __syncthreads();
        int* t = cur; cur = nxt; nxt = t;
    }
    int incl = cur[tid];
    int excl = incl - v;
    if (tid < CAP) {
        g_rowptr[tid] = excl;
        g_invdeg[tid] = 1.0f / fmaxf((float)v, 1.0f);
        if (tid == CAP - 1) g_rowptr[CAP] = incl;
    }

    if (tid < CAP) {
        int k = excl;
        #pragma unroll 8
        for (int e = 0; e < E_SP; e++)
            if (s_dst[e] == tid) g_col[k++] = s_src[e];
    }

    {
        int i = tid >> 4, j = tid & 15;
        int cnt = 0;
        #pragma unroll
        for (int e = 0; e < E_FT; e++)
            if (s_fe[E_FT + e] == i && s_fe[e] == j) cnt++;
        s_cnt[i][j] = cnt;
    }
    __syncthreads();
    {
        int i = tid >> 4, j = tid & 15;
        int dsum = 0;
        #pragma unroll
        for (int jj = 0; jj < INV; jj++) dsum += s_cnt[i][jj];
        s_A[i][j] = (float)s_cnt[i][j] / fmaxf((float)dsum, 1.0f);
    }
    __syncthreads();

    {
        int r = tid >> 4, o = tid & 15;
        float g1 = 0.f, g2 = 0.f, b1 = 0.f;
        #pragma unroll
        for (int i = 0; i < INV; i++) {
            float f1 = s_fcw[i * INV + o];
            float f2 = s_fcw[(INV + i) * INV + o];
            g1 += s_Wl[r * INV + i] * f1;
            g2 += s_Wr[r * INV + i] * f1;
            b1 += s_A[i][r] * f2;
        }
        g_G1[r][o] = g1; g_G2[r][o] = g2; g_B1[r][o] = b1;
        g_F2[r][o] = s_fcw[(INV + r) * INV + o];
        #pragma unroll
        for (int k = 0; k < 5; k++) {
            float vv = 0.f;
            #pragma unroll
            for (int o2 = 0; o2 < INV; o2++) {
                float w5 = s_c2[(o2 * INV + r) * 5 + k];
                if (k >= 1 && k <= 3) w5 += s_c1[(o2 * INV + r) * 3 + (k - 1)];
                vv += w5 * s_fcw[(32 + o2) * INV + o];
            }
            g_V[k][r][o] = vv;
        }
        if (r == 0) {
            float cs = 0.f, cv = 0.f;
            #pragma unroll
            for (int i = 0; i < INV; i++) {
                cs += s_fcw[(INV + i) * INV + o];
                cv += s_bl[i] * s_fcw[i * INV + o];
            }
            g_csF2[o] = cs;
            g_const[o] = cv + s_fcb[o];
        }
    }
}

// ---------------- main fused kernel: one (b,c) slice per block --------------
// 160 threads; tid<144 active: sp = tid>>1, h = tid&1; each thread owns
// s ∈ {sp, sp+72} x channels [8h, 8h+8). All MAC streams use fma.rn.f32x2.
__global__ __launch_bounds__(NTHR, 5)
void stconv_kernel(const float* __restrict__ src,
                   const float* __restrict__ fbl,
                   float* __restrict__ out) {
    __shared__ __align__(16) float sX[INV][XSTR];
    __shared__ __align__(16) float sYA[SEQ][YSTR];
    __shared__ __align__(16) float sYF[SEQ][YSTR];
    __shared__ __align__(16) float sG1[INV][INV], sG2[INV][INV], sB1[INV][INV], sF2[INV][INV];
    __shared__ __align__(16) float sV[5][INV][INV];
    __shared__ __align__(16) float sCs[INV], sC0[INV];

    const int c = blockIdx.x, b = blockIdx.y;
    const int tid = threadIdx.x;
    const bool act = tid < 144;
    const int sp = tid >> 1;    // 0..71
    const int h  = tid & 1;
    const int q  = 2 * h;       // float4 (=ulonglong2) index of channel half
    const int base = ((b * CAP + c) * SEQ) * INV;

    for (int idx = tid; idx < INV * INV; idx += NTHR) {
        int r = idx >> 4, o = idx & 15;
        sG1[r][o] = g_G1[r][o]; sG2[r][o] = g_G2[r][o];
        sB1[r][o] = g_B1[r][o]; sF2[r][o] = g_F2[r][o];
        #pragma unroll
        for (int k = 0; k < 5; k++) sV[k][r][o] = g_V[k][r][o];
        if (r == 0) { sCs[o] = g_csF2[o]; sC0[o] = g_const[o]; }
    }
    if (tid < 2 * INV) {
        sX[tid >> 1][tid & 1] = 0.f;
    } else if (tid < 2 * INV + (XSTR - SEQ - SOFF) * INV) {
        int g = tid - 2 * INV;
        sX[g % INV][SEQ + SOFF + g / INV] = 0.f;
    }

    if (act) {
        const float4* p = (const float4*)(src + base + tid * INV);
        float4 a0 = p[0], a1 = p[1], a2 = p[2], a3 = p[3];
        int ss = tid + SOFF;
        sX[0][ss]=a0.x;  sX[1][ss]=a0.y;  sX[2][ss]=a0.z;  sX[3][ss]=a0.w;
        sX[4][ss]=a1.x;  sX[5][ss]=a1.y;  sX[6][ss]=a1.z;  sX[7][ss]=a1.w;
        sX[8][ss]=a2.x;  sX[9][ss]=a2.y;  sX[10][ss]=a2.z; sX[11][ss]=a2.w;
        sX[12][ss]=a3.x; sX[13][ss]=a3.y; sX[14][ss]=a3.z; sX[15][ss]=a3.w;
    }
    __syncthreads();

    u64 acc[2][4];   // [m][4 x f32x2 = 8 channels]
    if (act) {
        const int r0 = g_rowptr[c], r1 = g_rowptr[c + 1];
        const float sc = g_invdeg[c];

        #pragma unroll
        for (int m = 0; m < 2; m++) {
            const int s  = sp + 72 * m;
            const int ss = s + SOFF;

            // YA/YF half-row for (s, h), packed f32x2
            {
                u64 ya0=0,ya1=0,ya2=0,ya3=0, yf0=0,yf1=0,yf2=0,yf3=0;
                #pragma unroll
                for (int j = 0; j < 16; j++) {
                    u64 xv = splat2(sX[j][ss]);
                    const ulonglong2* br = (const ulonglong2*)sB1[j];
                    const ulonglong2* fr = (const ulonglong2*)sF2[j];
                    ulonglong2 b0 = br[q], b1 = br[q + 1];
                    ulonglong2 f0 = fr[q], f1 = fr[q + 1];
                    ya0 = ffma2(xv, b0.x, ya0); ya1 = ffma2(xv, b0.y, ya1);
                    ya2 = ffma2(xv, b1.x, ya2); ya3 = ffma2(xv, b1.y, ya3);
                    yf0 = ffma2(xv, f0.x, yf0); yf1 = ffma2(xv, f0.y, yf1);
                    yf2 = ffma2(xv, f1.x, yf2); yf3 = ffma2(xv, f1.y, yf3);
                }
                ulonglong2* yaw = (ulonglong2*)sYA[s];
                ulonglong2* yfw = (ulonglong2*)sYF[s];
                yaw[q] = make_ulonglong2(ya0, ya1); yaw[q + 1] = make_ulonglong2(ya2, ya3);
                yfw[q] = make_ulonglong2(yf0, yf1); yfw[q + 1] = make_ulonglong2(yf2, yf3);
            }

            // constant + fgcn_bl term
            {
                u64 fbls = splat2(__ldg(fbl + s));
                ulonglong2 c0a = ((const ulonglong2*)sC0)[q], c0b = ((const ulonglong2*)sC0)[q + 1];
                ulonglong2 csa = ((const ulonglong2*)sCs)[q], csb = ((const ulonglong2*)sCs)[q + 1];
                acc[m][0] = ffma2(fbls, csa.x, c0a.x);
                acc[m][1] = ffma2(fbls, csa.y, c0a.y);
                acc[m][2] = ffma2(fbls, csb.x, c0b.x);
                acc[m][3] = ffma2(fbls, csb.y, c0b.y);
            }

            // spatial: gather mean (scalar FADD, then packed fold)
            {
                float4 m0 = {0,0,0,0}, m1 = {0,0,0,0}, m2 = {0,0,0,0}, m3 = {0,0,0,0};
                for (int e = r0; e < r1; e++) {
                    int nb = g_col[e];
                    const float4* p = (const float4*)(src + ((b * CAP + nb) * SEQ + s) * INV);
                    float4 a0 = __ldg(p), a1 = __ldg(p + 1), a2 = __ldg(p + 2), a3 = __ldg(p + 3);
                    m0.x+=a0.x; m0.y+=a0.y; m0.z+=a0.z; m0.w+=a0.w;
                    m1.x+=a1.x; m1.y+=a1.y; m1.z+=a1.z; m1.w+=a1.w;
                    m2.x+=a2.x; m2.y+=a2.y; m2.z+=a2.z; m2.w+=a2.w;
                    m3.x+=a3.x; m3.y+=a3.y; m3.z+=a3.z; m3.w+=a3.w;
                }
                float mg[16] = {m0.x*sc,m0.y*sc,m0.z*sc,m0.w*sc, m1.x*sc,m1.y*sc,m1.z*sc,m1.w*sc,
                                m2.x*sc,m2.y*sc,m2.z*sc,m2.w*sc, m3.x*sc,m3.y*sc,m3.z*sc,m3.w*sc};
                #pragma unroll
                for (int j = 0; j < 16; j++) {
                    u64 mm = splat2(mg[j]);
                    u64 xv = splat2(sX[j][ss]);
                    const ulonglong2* g1r = (const ulonglong2*)sG1[j];
                    const ulonglong2* g2r = (const ulonglong2*)sG2[j];
                    ulonglong2 g1a = g1r[q], g1b = g1r[q + 1];
                    ulonglong2 g2a = g2r[q], g2b = g2r[q + 1];
                    acc[m][0] = ffma2(mm, g1a.x, acc[m][0]); acc[m][1] = ffma2(mm, g1a.y, acc[m][1]);
                    acc[m][2] = ffma2(mm, g1b.x, acc[m][2]); acc[m][3] = ffma2(mm, g1b.y, acc[m][3]);
                    acc[m][0] = ffma2(xv, g2a.x, acc[m][0]); acc[m][1] = ffma2(xv, g2a.y, acc[m][1]);
                    acc[m][2] = ffma2(xv, g2b.x, acc[m][2]); acc[m][3] = ffma2(xv, g2b.y, acc[m][3]);
                }
            }
        }

        // temporal: merged over the two s-positions, packed
        {
            const int ss0 = sp + SOFF, ss1 = sp + 72 + SOFF;
            #pragma unroll
            for (int k = 0; k < 5; k++) {
                #pragma unroll
                for (int j = 0; j < 16; j++) {
                    const ulonglong2* vr = (const ulonglong2*)sV[k][j];
                    ulonglong2 va = vr[q], vb = vr[q + 1];
                    u64 x0 = splat2(sX[j][ss0 + k - 2]);
                    u64 x1 = splat2(sX[j][ss1 + k - 2]);
                    acc[0][0] = ffma2(x0, va.x, acc[0][0]); acc[0][1] = ffma2(x0, va.y, acc[0][1]);
                    acc[0][2] = ffma2(x0, vb.x, acc[0][2]); acc[0][3] = ffma2(x0, vb.y, acc[0][3]);
                    acc[1][0] = ffma2(x1, va.x, acc[1][0]); acc[1][1] = ffma2(x1, va.y, acc[1][1]);
                    acc[1][2] = ffma2(x1, vb.x, acc[1][2]); acc[1][3] = ffma2(x1, vb.y, acc[1][3]);
                }
            }
        }
    }
    __syncthreads();

    if (act) {
        // big GEMM: both s-positions share each Y row read; 16 FFMA2/t
        const int s0 = sp, s1 = sp + 72;
        const float2* wp = g_W2;
        #pragma unroll 4
        for (int t = 0; t < SEQ; t++) {
            float2 wA = __ldg(wp + t * SEQ + s0);
            float2 wB = __ldg(wp + t * SEQ + s1);
            u64 aX = splat2(wA.x), aY = splat2(wA.y);
            u64 bX = splat2(wB.x), bY = splat2(wB.y);
            const ulonglong2* yap = (const ulonglong2*)sYA[t];
            const ulonglong2* yfp = (const ulonglong2*)sYF[t];
            ulonglong2 u0 = yap[q], u1 = yap[q + 1];
            ulonglong2 v0 = yfp[q], v1 = yfp[q + 1];
            acc[0][0] = ffma2(aX, u0.x, acc[0][0]); acc[0][0] = ffma2(aY, v0.x, acc[0][0]);
            acc[0][1] = ffma2(aX, u0.y, acc[0][1]); acc[0][1] = ffma2(aY, v0.y, acc[0][1]);
            acc[0][2] = ffma2(aX, u1.x, acc[0][2]); acc[0][2] = ffma2(aY, v1.x, acc[0][2]);
            acc[0][3] = ffma2(aX, u1.y, acc[0][3]); acc[0][3] = ffma2(aY, v1.y, acc[0][3]);
            acc[1][0] = ffma2(bX, u0.x, acc[1][0]); acc[1][0] = ffma2(bY, v0.x, acc[1][0]);
            acc[1][1] = ffma2(bX, u0.y, acc[1][1]); acc[1][1] = ffma2(bY, v0.y, acc[1][1]);
            acc[1][2] = ffma2(bX, u1.x, acc[1][2]); acc[1][2] = ffma2(bY, v1.x, acc[1][2]);
            acc[1][3] = ffma2(bX, u1.y, acc[1][3]); acc[1][3] = ffma2(bY, v1.y, acc[1][3]);
        }

        // out = src + contributions, fully packed stores
        #pragma unroll
        for (int m = 0; m < 2; m++) {
            const int s  = sp + 72 * m;
            const int ss = s + SOFF;
            const int ob = 8 * h;
            u64 x01 = pack2(sX[ob+0][ss], sX[ob+1][ss]);
            u64 x23 = pack2(sX[ob+2][ss], sX[ob+3][ss]);
            u64 x45 = pack2(sX[ob+4][ss], sX[ob+5][ss]);
            u64 x67 = pack2(sX[ob+6][ss], sX[ob+7][ss]);
            ulonglong2* po = (ulonglong2*)(out + base + s * INV);
            po[q]     = make_ulonglong2(add2(x01, acc[m][0]), add2(x23, acc[m][1]));
            po[q + 1] = make_ulonglong2(add2(x45, acc[m][2]), add2(x67, acc[m][3]));
        }
    }
}

// ---------------- launch ----------------------------------------------------
extern "C" void kernel_launch(void* const* d_in, const int* in_sizes, int n_in,
                              void* d_out, int out_size) {
    const float* src = (const float*)d_in[0];
    const int*   gei = (const int*)d_in[1];
    const int*   fei = (const int*)d_in[2];
    const float* Wl  = (const float*)d_in[3];
    const float* bl  = (const float*)d_in[4];
    const float* Wr  = (const float*)d_in[5];
    const float* fWl = (const float*)d_in[6];
    const float* fbl = (const float*)d_in[7];
    const float* fWr = (const float*)d_in[8];
    const float* c1w = (const float*)d_in[9];
    const float* c2w = (const float*)d_in[10];
    const float* fcw = (const float*)d_in[11];
    const float* fcb = (const float*)d_in[12];

    prep_all<<<1 + (SEQ * SEQ) / 256, 256>>>(gei, fei, Wl, bl, Wr, c1w, c2w, fcw, fcb, fWl, fWr);
    dim3 grid(CAP, BZ);
    stconv_kernel<<<grid, NTHR>>>(src, fbl, (float*)d_out);
}